// round 11
// baseline (speedup 1.0000x reference)
#include <cuda_runtime.h>
#include <math.h>

#define NLAT 61
#define NLON 120
#define NSEG (NLAT*NLON)      // 7320
#define CCH  64
#define ATT_SCALE 0.25f       // 1/sqrt(16)
#define LNEPS 1e-6f
// worst-case padded payload entries: (61*7*120 + 61*8) * 120 < 6.21M
#define EPAY_MAX 6400000

// Scratch (allocation-free rule: __device__ globals)
__device__ float g_xt [NSEG*CCH];    // x transposed to [p][c]
__device__ float g_q  [NSEG*CCH];    // pre-scaled by ATT_SCALE
__device__ float g_kv [NSEG*2*CCH];  // interleaved: [p][0:64]=k, [p][64:128]=v
__device__ float g_att[NSEG*CCH];
__device__ int   g_row_start[NLAT+1];  // original edge-row prefix
__device__ int   g_row_lenp [NLAT];    // padded row length (multiple of 8)
__device__ int   g_row_basep[NLAT];    // padded payload prefix (entry units)
__device__ int2  g_epay[EPAY_MAX];     // (kv byte offset, quad_w bits), seg-contiguous
// transposed weights: lane-contiguous layouts
__device__ float g_wq_t[4096];
__device__ float g_wk_t[4096];
__device__ float g_wv_t[4096];
__device__ float g_wo_t[4096];
__device__ float g_w1_t[8192];      // [c*128+f]
__device__ float g_w2_t[8192];      // [f*64+c]

// ---------------------------------------------------------------------------
// Kernel 0 (merged prep): blocks 0..28 transpose x -> [p][c]; block 29
// transposes weights; block 30 builds the edge row-pointer tables
// (concurrent with the rest -> its latency is hidden).
// ---------------------------------------------------------------------------
__global__ void k_prep(const float* __restrict__ x,
                       const float* __restrict__ wq, const float* __restrict__ wk,
                       const float* __restrict__ wv, const float* __restrict__ wo,
                       const float* __restrict__ w1, const float* __restrict__ w2,
                       const int* __restrict__ out_idx, int NE) {
    int tid = threadIdx.x;
    if (blockIdx.x < 29) {
        int p = blockIdx.x * 256 + tid;
        if (p < NSEG) {
            #pragma unroll
            for (int c4 = 0; c4 < 64; c4 += 4) {
                float4 t;
                t.x = __ldcs(&x[(c4+0)*NSEG + p]);
                t.y = __ldcs(&x[(c4+1)*NSEG + p]);
                t.z = __ldcs(&x[(c4+2)*NSEG + p]);
                t.w = __ldcs(&x[(c4+3)*NSEG + p]);
                *(float4*)&g_xt[p*64 + c4] = t;
            }
        }
    } else if (blockIdx.x == 29) {
        for (int i = tid; i < 4096; i += 256) {
            int o = i >> 6, c = i & 63;
            g_wq_t[c*64+o] = wq[i];
            g_wk_t[c*64+o] = wk[i];
            g_wv_t[c*64+o] = wv[i];
            g_wo_t[c*64+o] = wo[i];
        }
        for (int i = tid; i < 8192; i += 256) {    // w1: [f][c] -> [c][f]
            int f = i >> 6, c = i & 63;
            g_w1_t[c*128+f] = w1[i];
        }
        for (int i = tid; i < 8192; i += 256) {    // w2: [c][f] -> [f][c]
            int c = i >> 7, f = i & 127;
            g_w2_t[f*64+c] = w2[i];
        }
    } else {
        __shared__ int cnt[NLAT];
        if (tid < NLAT) cnt[tid] = 0;
        __syncthreads();
        for (int e = tid; e < NE; e += 256) {
            int row = __ldg(&out_idx[e * 120]) / 120;
            atomicAdd(&cnt[row], 1);
        }
        __syncthreads();
        if (tid == 0) {
            int acc = 0, accp = 0;
            for (int r = 0; r < NLAT; ++r) {
                g_row_start[r] = acc; acc += cnt[r];
                int lenp = (cnt[r] + 7) & ~7;
                g_row_lenp[r]  = lenp;
                g_row_basep[r] = accp; accp += lenp * 120;
            }
            g_row_start[NLAT] = acc;
        }
    }
}

// ---------------------------------------------------------------------------
// Kernel 0c: payload build, massively parallel (61 x 15 blocks). Row ho,
// segment column wo, edge j: (kv_byte_off, quad_w bits). Rows padded to
// lenp with (0, 0.0f) -> exact zero contribution, branch-free hot loop.
// ---------------------------------------------------------------------------
__global__ void __launch_bounds__(256) k_pay(const int* __restrict__ in_idx,
                                             const float* __restrict__ quad_w) {
    int ho   = blockIdx.x;
    int rs   = g_row_start[ho];
    int len  = g_row_start[ho+1] - rs;
    int lenp = g_row_lenp[ho];
    int base = g_row_basep[ho];
    int tot  = lenp * 120;
    #pragma unroll 2
    for (int t = blockIdx.y * 256 + threadIdx.x; t < tot; t += gridDim.y * 256) {
        int j = t / 120, wo = t - j*120;           // j-major: coalesced in_idx reads
        int2 pay = make_int2(0, 0);
        if (j < len) {
            int s = __ldg(&in_idx[(rs+j)*120 + wo]);
            pay = make_int2(s * 512, __float_as_int(__ldg(&quad_w[s])));
        }
        g_epay[base + wo*lenp + j] = pay;
    }
}

// ---------------------------------------------------------------------------
// Kernel 1: LayerNorm0 + Q/K/V. One warp per 2 positions (P=2): grid 458
// blocks -> ~3 blocks/SM (was grid-starved at 229). q pre-scaled; k/v
// interleaved into g_kv.
// ---------------------------------------------------------------------------
__global__ void __launch_bounds__(256) k_ln_qkv(const float* __restrict__ ln_g,
                                                const float* __restrict__ ln_b) {
    __shared__ float sH[8*2*64];   // 4 KB
    int tid = threadIdx.x, warp = tid >> 5, lane = tid & 31;
    int pbase = blockIdx.x * 16 + warp * 2;
    if (pbase >= NSEG) return;
    int c0 = 2*lane, c1 = c0 + 1;
    float* mH = sH + warp*128;

    float2 xv[2]; float s0[2];
    #pragma unroll
    for (int u = 0; u < 2; ++u) {
        xv[u] = *(const float2*)&g_xt[(pbase+u)*64 + c0];
        s0[u] = xv[u].x + xv[u].y;
    }
    #pragma unroll
    for (int off = 16; off; off >>= 1) {
        #pragma unroll
        for (int u = 0; u < 2; ++u) s0[u] += __shfl_xor_sync(0xffffffffu, s0[u], off);
    }
    float da[2], db[2], vs[2];
    #pragma unroll
    for (int u = 0; u < 2; ++u) {
        float mean = s0[u] * (1.0f/64.0f);
        da[u] = xv[u].x - mean; db[u] = xv[u].y - mean;
        vs[u] = da[u]*da[u] + db[u]*db[u];
    }
    #pragma unroll
    for (int off = 16; off; off >>= 1) {
        #pragma unroll
        for (int u = 0; u < 2; ++u) vs[u] += __shfl_xor_sync(0xffffffffu, vs[u], off);
    }
    float g0 = ln_g[c0], g1 = ln_g[c1], be0 = ln_b[c0], be1 = ln_b[c1];
    #pragma unroll
    for (int u = 0; u < 2; ++u) {
        float rstd = rsqrtf(vs[u] * (1.0f/64.0f) + LNEPS);
        mH[u*64 + c0] = da[u]*rstd*g0 + be0;
        mH[u*64 + c1] = db[u]*rstd*g1 + be1;
    }
    __syncwarp();

    float aq[2][2] = {}, ak[2][2] = {}, av[2][2] = {};
    #pragma unroll 8
    for (int c = 0; c < 64; ++c) {
        float2 wq2 = __ldg((const float2*)&g_wq_t[c*64 + c0]);
        float2 wk2 = __ldg((const float2*)&g_wk_t[c*64 + c0]);
        float2 wv2 = __ldg((const float2*)&g_wv_t[c*64 + c0]);
        #pragma unroll
        for (int u = 0; u < 2; ++u) {
            float hc = mH[u*64 + c];
            aq[u][0] = fmaf(wq2.x, hc, aq[u][0]); aq[u][1] = fmaf(wq2.y, hc, aq[u][1]);
            ak[u][0] = fmaf(wk2.x, hc, ak[u][0]); ak[u][1] = fmaf(wk2.y, hc, ak[u][1]);
            av[u][0] = fmaf(wv2.x, hc, av[u][0]); av[u][1] = fmaf(wv2.y, hc, av[u][1]);
        }
    }
    #pragma unroll
    for (int u = 0; u < 2; ++u) {
        int p = pbase + u;
        *(float2*)&g_q [p*64  + c0] =
            make_float2(aq[u][0]*ATT_SCALE, aq[u][1]*ATT_SCALE);
        *(float2*)&g_kv[p*128 + c0]      = make_float2(ak[u][0], ak[u][1]);
        *(float2*)&g_kv[p*128 + 64 + c0] = make_float2(av[u][0], av[u][1]);
    }
}

// ---------------------------------------------------------------------------
// Kernel 2: neighborhood attention. One warp per segment, 4 edges per
// warp-instruction (quarter = lane>>3). Lane l owns channels {4l..4l+3}
// (heads 0/1) and {32+4l..32+4l+3} (heads 2/3): every LDG.128 is 128B
// contiguous per row -> 4 wavefronts (line floor). Two per-half scores,
// each reduced with 2 shfls. Padded entries carry qw=0.
// ---------------------------------------------------------------------------
__global__ void __launch_bounds__(256) k_attn() {
    int b = blockIdx.x;
    int bp = (b & 1) ? (914 - (b >> 1)) : (b >> 1);   // heavy pole rows first
    int warp = threadIdx.x >> 5, lane = threadIdx.x & 31;
    int p = bp * 8 + warp;
    int ho = p / 120, wo = p - ho * 120;
    int quarter = lane >> 3;              // edge slot within group-of-4
    int l = lane & 7;
    int ca = 4*l;                         // head l>>2     (0 or 1)
    int cb = 32 + 4*l;                    // head 2+(l>>2) (2 or 3)

    float4 qa = *(const float4*)&g_q[p*64 + ca];
    float4 qb = *(const float4*)&g_q[p*64 + cb];

    int lenp = g_row_lenp[ho];
    const int2* pay = &g_epay[g_row_basep[ho] + wo*lenp + quarter];

    float dena = 0.f, denb = 0.f;
    float4 na = make_float4(0.f,0.f,0.f,0.f);
    float4 nb = make_float4(0.f,0.f,0.f,0.f);

    const char* kvb = (const char*)g_kv;
    int ngrp = lenp >> 2;                 // groups of 4 edges (lenp % 8 == 0)
    #pragma unroll 1
    for (int i = 0; i < ngrp; i += 2) {
        int2 p0 = __ldg(&pay[(i  )*4]);
        int2 p1 = __ldg(&pay[(i+1)*4]);
        const char* k0 = kvb + p0.x;
        const char* k1 = kvb + p1.x;
        float4 ka0 = *(const float4*)(k0 + ca*4);
        float4 kb0 = *(const float4*)(k0 + cb*4);
        float4 va0 = *(const float4*)(k0 + 256 + ca*4);
        float4 vb0 = *(const float4*)(k0 + 256 + cb*4);
        float4 ka1 = *(const float4*)(k1 + ca*4);
        float4 kb1 = *(const float4*)(k1 + cb*4);
        float4 va1 = *(const float4*)(k1 + 256 + ca*4);
        float4 vb1 = *(const float4*)(k1 + 256 + cb*4);

        float sa0 = ka0.x*qa.x + ka0.y*qa.y + ka0.z*qa.z + ka0.w*qa.w;
        float sb0 = kb0.x*qb.x + kb0.y*qb.y + kb0.z*qb.z + kb0.w*qb.w;
        float sa1 = ka1.x*qa.x + ka1.y*qa.y + ka1.z*qa.z + ka1.w*qa.w;
        float sb1 = kb1.x*qb.x + kb1.y*qb.y + kb1.z*qb.z + kb1.w*qb.w;
        sa0 += __shfl_xor_sync(0xffffffffu, sa0, 1);
        sb0 += __shfl_xor_sync(0xffffffffu, sb0, 1);
        sa1 += __shfl_xor_sync(0xffffffffu, sa1, 1);
        sb1 += __shfl_xor_sync(0xffffffffu, sb1, 1);
        sa0 += __shfl_xor_sync(0xffffffffu, sa0, 2);
        sb0 += __shfl_xor_sync(0xffffffffu, sb0, 2);
        sa1 += __shfl_xor_sync(0xffffffffu, sa1, 2);
        sb1 += __shfl_xor_sync(0xffffffffu, sb1, 2);
        float w0 = __int_as_float(p0.y);
        float w1 = __int_as_float(p1.y);
        float pa0 = __expf(sa0) * w0, pb0 = __expf(sb0) * w0;
        float pa1 = __expf(sa1) * w1, pb1 = __expf(sb1) * w1;
        dena += pa0; denb += pb0;
        na.x = fmaf(pa0, va0.x, na.x); na.y = fmaf(pa0, va0.y, na.y);
        na.z = fmaf(pa0, va0.z, na.z); na.w = fmaf(pa0, va0.w, na.w);
        nb.x = fmaf(pb0, vb0.x, nb.x); nb.y = fmaf(pb0, vb0.y, nb.y);
        nb.z = fmaf(pb0, vb0.z, nb.z); nb.w = fmaf(pb0, vb0.w, nb.w);
        dena += pa1; denb += pb1;
        na.x = fmaf(pa1, va1.x, na.x); na.y = fmaf(pa1, va1.y, na.y);
        na.z = fmaf(pa1, va1.z, na.z); na.w = fmaf(pa1, va1.w, na.w);
        nb.x = fmaf(pb1, vb1.x, nb.x); nb.y = fmaf(pb1, vb1.y, nb.y);
        nb.z = fmaf(pb1, vb1.z, nb.z); nb.w = fmaf(pb1, vb1.w, nb.w);
    }
    // reduce across the four edge quarters (same l -> same channels)
    #pragma unroll
    for (int off = 8; off <= 16; off <<= 1) {
        dena += __shfl_xor_sync(0xffffffffu, dena, off);
        denb += __shfl_xor_sync(0xffffffffu, denb, off);
        na.x += __shfl_xor_sync(0xffffffffu, na.x, off);
        na.y += __shfl_xor_sync(0xffffffffu, na.y, off);
        na.z += __shfl_xor_sync(0xffffffffu, na.z, off);
        na.w += __shfl_xor_sync(0xffffffffu, na.w, off);
        nb.x += __shfl_xor_sync(0xffffffffu, nb.x, off);
        nb.y += __shfl_xor_sync(0xffffffffu, nb.y, off);
        nb.z += __shfl_xor_sync(0xffffffffu, nb.z, off);
        nb.w += __shfl_xor_sync(0xffffffffu, nb.w, off);
    }
    if (quarter == 0) {
        float inva = 1.0f / dena;
        float invb = 1.0f / denb;
        *(float4*)&g_att[p*64 + ca] =
            make_float4(na.x*inva, na.y*inva, na.z*inva, na.w*inva);
        *(float4*)&g_att[p*64 + cb] =
            make_float4(nb.x*invb, nb.y*invb, nb.z*invb, nb.w*invb);
    }
}

// ---------------------------------------------------------------------------
// Kernel 3: fused epilogue, P=2 positions per warp (grid 458, was starved
// at 229), L1-resident __ldg weights.
// ---------------------------------------------------------------------------
__global__ void __launch_bounds__(256) k_epilogue(const float* __restrict__ b1,
                                                  const float* __restrict__ b2,
                                                  const float* __restrict__ ln_g,
                                                  const float* __restrict__ ln_b,
                                                  float* __restrict__ out) {
    __shared__ float sV[8*2*64];    // 4 KB
    __shared__ float sT[8*2*128];   // 8 KB
    int tid = threadIdx.x, warp = tid >> 5, lane = tid & 31;
    int pbase = blockIdx.x * 16 + warp * 2;
    if (pbase >= NSEG) return;
    int c0 = 2*lane, c1 = c0 + 1;
    float* mV = sV + warp*128;
    float* mT = sT + warp*256;

    #pragma unroll
    for (int u = 0; u < 2; ++u) {
        float2 a2 = *(const float2*)&g_att[(pbase+u)*64 + c0];
        mV[u*64 + c0] = a2.x; mV[u*64 + c1] = a2.y;
    }
    __syncwarp();

    // a = wo @ att
    float acc[2][2] = {};
    #pragma unroll 8
    for (int c = 0; c < 64; ++c) {
        float2 w = __ldg((const float2*)&g_wo_t[c*64 + c0]);
        #pragma unroll
        for (int u = 0; u < 2; ++u) {
            float hc = mV[u*64 + c];
            acc[u][0] = fmaf(w.x, hc, acc[u][0]);
            acc[u][1] = fmaf(w.y, hc, acc[u][1]);
        }
    }
    // x1 = a + x ; LN1
    float x1a[2], x1b[2], s0[2];
    #pragma unroll
    for (int u = 0; u < 2; ++u) {
        float2 xv = *(const float2*)&g_xt[(pbase+u)*64 + c0];
        x1a[u] = acc[u][0] + xv.x;
        x1b[u] = acc[u][1] + xv.y;
        s0[u] = x1a[u] + x1b[u];
    }
    #pragma unroll
    for (int off = 16; off; off >>= 1) {
        #pragma unroll
        for (int u = 0; u < 2; ++u) s0[u] += __shfl_xor_sync(0xffffffffu, s0[u], off);
    }
    float da[2], db[2], vs[2];
    #pragma unroll
    for (int u = 0; u < 2; ++u) {
        float mean = s0[u] * (1.0f/64.0f);
        da[u] = x1a[u] - mean; db[u] = x1b[u] - mean;
        vs[u] = da[u]*da[u] + db[u]*db[u];
    }
    #pragma unroll
    for (int off = 16; off; off >>= 1) {
        #pragma unroll
        for (int u = 0; u < 2; ++u) vs[u] += __shfl_xor_sync(0xffffffffu, vs[u], off);
    }
    float g0 = ln_g[c0], g1 = ln_g[c1], be0 = ln_b[c0], be1 = ln_b[c1];
    __syncwarp();   // all lanes done reading mV in the wo loop
    #pragma unroll
    for (int u = 0; u < 2; ++u) {
        float rstd = rsqrtf(vs[u] * (1.0f/64.0f) + LNEPS);
        mV[u*64 + c0] = da[u]*rstd*g0 + be0;
        mV[u*64 + c1] = db[u]*rstd*g1 + be1;
    }
    __syncwarp();

    // t = gelu(w1 @ h1 + b1)
    float t[2][4] = {};
    #pragma unroll 8
    for (int c = 0; c < 64; ++c) {
        float2 wA = __ldg((const float2*)&g_w1_t[c*128 + c0]);
        float2 wB = __ldg((const float2*)&g_w1_t[c*128 + 64 + c0]);
        #pragma unroll
        for (int u = 0; u < 2; ++u) {
            float hc = mV[u*64 + c];
            t[u][0] = fmaf(wA.x, hc, t[u][0]); t[u][1] = fmaf(wA.y, hc, t[u][1]);
            t[u][2] = fmaf(wB.x, hc, t[u][2]); t[u][3] = fmaf(wB.y, hc, t[u][3]);
        }
    }
    const float RS2 = 0.70710678118654752f;
    float bb0 = b1[c0], bb1 = b1[c1], bb2 = b1[64+c0], bb3 = b1[64+c1];
    #pragma unroll
    for (int u = 0; u < 2; ++u) {
        float v0 = t[u][0] + bb0, v1 = t[u][1] + bb1;
        float v2 = t[u][2] + bb2, v3 = t[u][3] + bb3;
        mT[u*128 + c0]      = 0.5f*v0*(1.f + erff(v0*RS2));
        mT[u*128 + c1]      = 0.5f*v1*(1.f + erff(v1*RS2));
        mT[u*128 + 64 + c0] = 0.5f*v2*(1.f + erff(v2*RS2));
        mT[u*128 + 64 + c1] = 0.5f*v3*(1.f + erff(v3*RS2));
    }
    __syncwarp();

    // out = w2 @ t + b2 + x1
    float o[2][2] = {};
    #pragma unroll 8
    for (int f = 0; f < 128; ++f) {
        float2 w = __ldg((const float2*)&g_w2_t[f*64 + c0]);
        #pragma unroll
        for (int u = 0; u < 2; ++u) {
            float tf = mT[u*128 + f];
            o[u][0] = fmaf(w.x, tf, o[u][0]);
            o[u][1] = fmaf(w.y, tf, o[u][1]);
        }
    }
    float ob0 = b2[c0], ob1 = b2[c1];
    #pragma unroll
    for (int u = 0; u < 2; ++u) {
        int p = pbase + u;
        out[c0*NSEG + p] = o[u][0] + ob0 + x1a[u];
        out[c1*NSEG + p] = o[u][1] + ob1 + x1b[u];
    }
}

// ---------------------------------------------------------------------------
// Launch. Inputs: x, wq, wk, wv, wo, w1, b1, w2, b2, ln0_g, ln0_b,
// ln1_g, ln1_b, quad_w, out_idx, in_idx.
// ---------------------------------------------------------------------------
extern "C" void kernel_launch(void* const* d_in, const int* in_sizes, int n_in,
                              void* d_out, int out_size) {
    const float* x      = (const float*)d_in[0];
    const float* wq     = (const float*)d_in[1];
    const float* wk     = (const float*)d_in[2];
    const float* wv     = (const float*)d_in[3];
    const float* wmo    = (const float*)d_in[4];
    const float* w1     = (const float*)d_in[5];
    const float* b1     = (const float*)d_in[6];
    const float* w2     = (const float*)d_in[7];
    const float* b2     = (const float*)d_in[8];
    const float* ln0_g  = (const float*)d_in[9];
    const float* ln0_b  = (const float*)d_in[10];
    const float* ln1_g  = (const float*)d_in[11];
    const float* ln1_b  = (const float*)d_in[12];
    const float* quad_w = (const float*)d_in[13];
    const int*   out_idx= (const int*)d_in[14];
    const int*   in_idx = (const int*)d_in[15];
    float* out = (float*)d_out;

    int NNZ = in_sizes[14];
    int NE  = NNZ / 120;

    k_prep    <<<31, 256>>>(x, wq, wk, wv, wmo, w1, w2, out_idx, NE);
    k_pay     <<<dim3(61, 15), 256>>>(in_idx, quad_w);
    k_ln_qkv  <<<458, 256>>>(ln0_g, ln0_b);
    k_attn    <<<915, 256>>>();
    k_epilogue<<<458, 256>>>(b1, b2, ln1_g, ln1_b, out);
}

// round 12
// speedup vs baseline: 1.1649x; 1.1649x over previous
#include <cuda_runtime.h>
#include <math.h>

#define NLAT 61
#define NLON 120
#define NSEG (NLAT*NLON)      // 7320
#define CCH  64
#define ATT_SCALE 0.25f       // 1/sqrt(16)
#define LNEPS 1e-6f
// worst-case padded payload entries: (61*7*120 + 61*8) * 120 < 6.21M
#define EPAY_MAX 6400000

// Scratch (allocation-free rule: __device__ globals)
__device__ float g_xt [NSEG*CCH];    // x transposed to [p][c]
__device__ float g_q  [NSEG*CCH];    // pre-scaled by ATT_SCALE
__device__ float g_kv [NSEG*2*CCH];  // interleaved: [p][0:64]=k, [p][64:128]=v
__device__ float g_att[NSEG*CCH];
__device__ int   g_row_start[NLAT+1];  // original edge-row prefix
__device__ int   g_row_lenp [NLAT];    // padded row length (multiple of 8)
__device__ int   g_row_basep[NLAT];    // padded payload prefix (entry units)
__device__ int2  g_epay[EPAY_MAX];     // (kv byte offset, quad_w bits), seg-contiguous
// transposed weights: lane-contiguous layouts
__device__ float g_wq_t[4096];
__device__ float g_wk_t[4096];
__device__ float g_wv_t[4096];
__device__ float g_wo_t[4096];
__device__ float g_w1_t[8192];      // [c*128+f]
__device__ float g_w2_t[8192];      // [f*64+c]

// ---------------------------------------------------------------------------
// Kernel 0: per-output-row edge ranges + padded payload layout (1024 thr).
// ---------------------------------------------------------------------------
__global__ void k_rowptr(const int* __restrict__ out_idx, int NE) {
    __shared__ int cnt[NLAT];
    int tid = threadIdx.x;
    if (tid < NLAT) cnt[tid] = 0;
    __syncthreads();
    for (int e = tid; e < NE; e += blockDim.x) {
        int row = __ldg(&out_idx[e * 120]) / 120;
        atomicAdd(&cnt[row], 1);
    }
    __syncthreads();
    if (tid == 0) {
        int acc = 0, accp = 0;
        for (int r = 0; r < NLAT; ++r) {
            g_row_start[r] = acc; acc += cnt[r];
            int lenp = (cnt[r] + 7) & ~7;
            g_row_lenp[r]  = lenp;
            g_row_basep[r] = accp; accp += lenp * 120;
        }
        g_row_start[NLAT] = acc;
    }
}

// ---------------------------------------------------------------------------
// Kernel 0b: transpose x -> [p][c]; weights -> lane-contiguous layouts.
// ---------------------------------------------------------------------------
__global__ void k_prep(const float* __restrict__ x,
                       const float* __restrict__ wq, const float* __restrict__ wk,
                       const float* __restrict__ wv, const float* __restrict__ wo,
                       const float* __restrict__ w1, const float* __restrict__ w2) {
    int tid = threadIdx.x;
    if (blockIdx.x < 29) {
        int p = blockIdx.x * 256 + tid;
        if (p < NSEG) {
            #pragma unroll
            for (int c4 = 0; c4 < 64; c4 += 4) {
                float4 t;
                t.x = __ldcs(&x[(c4+0)*NSEG + p]);
                t.y = __ldcs(&x[(c4+1)*NSEG + p]);
                t.z = __ldcs(&x[(c4+2)*NSEG + p]);
                t.w = __ldcs(&x[(c4+3)*NSEG + p]);
                *(float4*)&g_xt[p*64 + c4] = t;
            }
        }
    } else {
        for (int i = tid; i < 4096; i += 256) {
            int o = i >> 6, c = i & 63;
            g_wq_t[c*64+o] = wq[i];
            g_wk_t[c*64+o] = wk[i];
            g_wv_t[c*64+o] = wv[i];
            g_wo_t[c*64+o] = wo[i];
        }
        for (int i = tid; i < 8192; i += 256) {    // w1: [f][c] -> [c][f]
            int f = i >> 6, c = i & 63;
            g_w1_t[c*128+f] = w1[i];
        }
        for (int i = tid; i < 8192; i += 256) {    // w2: [c][f] -> [f][c]
            int c = i >> 7, f = i & 127;
            g_w2_t[f*64+c] = w2[i];
        }
    }
}

// ---------------------------------------------------------------------------
// Kernel 0c: payload build, massively parallel (61 x 15 blocks).
// ---------------------------------------------------------------------------
__global__ void __launch_bounds__(256) k_pay(const int* __restrict__ in_idx,
                                             const float* __restrict__ quad_w) {
    int ho   = blockIdx.x;
    int rs   = g_row_start[ho];
    int len  = g_row_start[ho+1] - rs;
    int lenp = g_row_lenp[ho];
    int base = g_row_basep[ho];
    int tot  = lenp * 120;
    #pragma unroll 2
    for (int t = blockIdx.y * 256 + threadIdx.x; t < tot; t += gridDim.y * 256) {
        int j = t / 120, wo = t - j*120;           // j-major: coalesced in_idx reads
        int2 pay = make_int2(0, 0);
        if (j < len) {
            int s = __ldg(&in_idx[(rs+j)*120 + wo]);
            pay = make_int2(s * 512, __float_as_int(__ldg(&quad_w[s])));
        }
        g_epay[base + wo*lenp + j] = pay;
    }
}

// ---------------------------------------------------------------------------
// Kernel 1: LayerNorm0 + Q/K/V. One warp per 4 positions (P=4, the R10
// best configuration). q pre-scaled; k/v interleaved into g_kv.
// ---------------------------------------------------------------------------
__global__ void __launch_bounds__(256) k_ln_qkv(const float* __restrict__ ln_g,
                                                const float* __restrict__ ln_b) {
    __shared__ float sH[8*4*64];   // 8 KB
    int tid = threadIdx.x, warp = tid >> 5, lane = tid & 31;
    int pbase = blockIdx.x * 32 + warp * 4;
    if (pbase >= NSEG) return;
    int c0 = 2*lane, c1 = c0 + 1;
    float* mH = sH + warp*256;

    float2 xv[4]; float s0[4];
    #pragma unroll
    for (int u = 0; u < 4; ++u) {
        xv[u] = *(const float2*)&g_xt[(pbase+u)*64 + c0];
        s0[u] = xv[u].x + xv[u].y;
    }
    #pragma unroll
    for (int off = 16; off; off >>= 1) {
        #pragma unroll
        for (int u = 0; u < 4; ++u) s0[u] += __shfl_xor_sync(0xffffffffu, s0[u], off);
    }
    float da[4], db[4], vs[4];
    #pragma unroll
    for (int u = 0; u < 4; ++u) {
        float mean = s0[u] * (1.0f/64.0f);
        da[u] = xv[u].x - mean; db[u] = xv[u].y - mean;
        vs[u] = da[u]*da[u] + db[u]*db[u];
    }
    #pragma unroll
    for (int off = 16; off; off >>= 1) {
        #pragma unroll
        for (int u = 0; u < 4; ++u) vs[u] += __shfl_xor_sync(0xffffffffu, vs[u], off);
    }
    float g0 = ln_g[c0], g1 = ln_g[c1], be0 = ln_b[c0], be1 = ln_b[c1];
    #pragma unroll
    for (int u = 0; u < 4; ++u) {
        float rstd = rsqrtf(vs[u] * (1.0f/64.0f) + LNEPS);
        mH[u*64 + c0] = da[u]*rstd*g0 + be0;
        mH[u*64 + c1] = db[u]*rstd*g1 + be1;
    }
    __syncwarp();

    float aq[4][2] = {}, ak[4][2] = {}, av[4][2] = {};
    #pragma unroll 8
    for (int c = 0; c < 64; ++c) {
        float2 wq2 = __ldg((const float2*)&g_wq_t[c*64 + c0]);
        float2 wk2 = __ldg((const float2*)&g_wk_t[c*64 + c0]);
        float2 wv2 = __ldg((const float2*)&g_wv_t[c*64 + c0]);
        #pragma unroll
        for (int u = 0; u < 4; ++u) {
            float hc = mH[u*64 + c];
            aq[u][0] = fmaf(wq2.x, hc, aq[u][0]); aq[u][1] = fmaf(wq2.y, hc, aq[u][1]);
            ak[u][0] = fmaf(wk2.x, hc, ak[u][0]); ak[u][1] = fmaf(wk2.y, hc, ak[u][1]);
            av[u][0] = fmaf(wv2.x, hc, av[u][0]); av[u][1] = fmaf(wv2.y, hc, av[u][1]);
        }
    }
    #pragma unroll
    for (int u = 0; u < 4; ++u) {
        int p = pbase + u;
        *(float2*)&g_q [p*64  + c0] =
            make_float2(aq[u][0]*ATT_SCALE, aq[u][1]*ATT_SCALE);
        *(float2*)&g_kv[p*128 + c0]      = make_float2(ak[u][0], ak[u][1]);
        *(float2*)&g_kv[p*128 + 64 + c0] = make_float2(av[u][0], av[u][1]);
    }
}

// ---------------------------------------------------------------------------
// Kernel 2: neighborhood attention, TWO warps per segment (4 segs/block,
// grid 1830). Warp pair parity 'par' takes alternating pairs of 4-edge
// groups (stride 4) of the padded stream -> pole-row critical path halved
// and wave balance improved. Within a warp: 4 edges per instruction
// (quarter = lane>>3); lane l owns channels {4l..4l+3} and {32+4l..32+4l+3}
// so every LDG.128 is one 128B line per row (wavefront floor). Partial
// (den, num) combined across the warp pair through smem.
// ---------------------------------------------------------------------------
__global__ void __launch_bounds__(256) k_attn() {
    __shared__ float sred[8][80];         // per warp: 8 lanes x 10 partials
    int b = blockIdx.x;
    int bp = (b & 1) ? (1829 - (b >> 1)) : (b >> 1);  // heavy pole rows first
    int warp = threadIdx.x >> 5, lane = threadIdx.x & 31;
    int p = bp * 4 + (warp >> 1);
    int par = warp & 1;                   // which half of the edge stream
    int ho = p / 120, wo = p - ho * 120;
    int quarter = lane >> 3;              // edge slot within group-of-4
    int l = lane & 7;
    int ca = 4*l;                         // heads 0/1 channels
    int cb = 32 + 4*l;                    // heads 2/3 channels

    float4 qa = *(const float4*)&g_q[p*64 + ca];
    float4 qb = *(const float4*)&g_q[p*64 + cb];

    int lenp = g_row_lenp[ho];
    const int2* pay = &g_epay[g_row_basep[ho] + wo*lenp + quarter];

    float dena = 0.f, denb = 0.f;
    float4 na = make_float4(0.f,0.f,0.f,0.f);
    float4 nb = make_float4(0.f,0.f,0.f,0.f);

    const char* kvb = (const char*)g_kv;
    int ngrp = lenp >> 2;                 // groups of 4 edges; ngrp even
    #pragma unroll 1
    for (int i = 2*par; i < ngrp; i += 4) {   // this warp: groups i, i+1
        int2 p0 = __ldg(&pay[(i  )*4]);
        int2 p1 = __ldg(&pay[(i+1)*4]);
        const char* k0 = kvb + p0.x;
        const char* k1 = kvb + p1.x;
        float4 ka0 = *(const float4*)(k0 + ca*4);
        float4 kb0 = *(const float4*)(k0 + cb*4);
        float4 va0 = *(const float4*)(k0 + 256 + ca*4);
        float4 vb0 = *(const float4*)(k0 + 256 + cb*4);
        float4 ka1 = *(const float4*)(k1 + ca*4);
        float4 kb1 = *(const float4*)(k1 + cb*4);
        float4 va1 = *(const float4*)(k1 + 256 + ca*4);
        float4 vb1 = *(const float4*)(k1 + 256 + cb*4);

        float sa0 = ka0.x*qa.x + ka0.y*qa.y + ka0.z*qa.z + ka0.w*qa.w;
        float sb0 = kb0.x*qb.x + kb0.y*qb.y + kb0.z*qb.z + kb0.w*qb.w;
        float sa1 = ka1.x*qa.x + ka1.y*qa.y + ka1.z*qa.z + ka1.w*qa.w;
        float sb1 = kb1.x*qb.x + kb1.y*qb.y + kb1.z*qb.z + kb1.w*qb.w;
        sa0 += __shfl_xor_sync(0xffffffffu, sa0, 1);
        sb0 += __shfl_xor_sync(0xffffffffu, sb0, 1);
        sa1 += __shfl_xor_sync(0xffffffffu, sa1, 1);
        sb1 += __shfl_xor_sync(0xffffffffu, sb1, 1);
        sa0 += __shfl_xor_sync(0xffffffffu, sa0, 2);
        sb0 += __shfl_xor_sync(0xffffffffu, sb0, 2);
        sa1 += __shfl_xor_sync(0xffffffffu, sa1, 2);
        sb1 += __shfl_xor_sync(0xffffffffu, sb1, 2);
        float w0 = __int_as_float(p0.y);
        float w1 = __int_as_float(p1.y);
        float pa0 = __expf(sa0) * w0, pb0 = __expf(sb0) * w0;
        float pa1 = __expf(sa1) * w1, pb1 = __expf(sb1) * w1;
        dena += pa0; denb += pb0;
        na.x = fmaf(pa0, va0.x, na.x); na.y = fmaf(pa0, va0.y, na.y);
        na.z = fmaf(pa0, va0.z, na.z); na.w = fmaf(pa0, va0.w, na.w);
        nb.x = fmaf(pb0, vb0.x, nb.x); nb.y = fmaf(pb0, vb0.y, nb.y);
        nb.z = fmaf(pb0, vb0.z, nb.z); nb.w = fmaf(pb0, vb0.w, nb.w);
        dena += pa1; denb += pb1;
        na.x = fmaf(pa1, va1.x, na.x); na.y = fmaf(pa1, va1.y, na.y);
        na.z = fmaf(pa1, va1.z, na.z); na.w = fmaf(pa1, va1.w, na.w);
        nb.x = fmaf(pb1, vb1.x, nb.x); nb.y = fmaf(pb1, vb1.y, nb.y);
        nb.z = fmaf(pb1, vb1.z, nb.z); nb.w = fmaf(pb1, vb1.w, nb.w);
    }
    // reduce across the four edge quarters (same l -> same channels)
    #pragma unroll
    for (int off = 8; off <= 16; off <<= 1) {
        dena += __shfl_xor_sync(0xffffffffu, dena, off);
        denb += __shfl_xor_sync(0xffffffffu, denb, off);
        na.x += __shfl_xor_sync(0xffffffffu, na.x, off);
        na.y += __shfl_xor_sync(0xffffffffu, na.y, off);
        na.z += __shfl_xor_sync(0xffffffffu, na.z, off);
        na.w += __shfl_xor_sync(0xffffffffu, na.w, off);
        nb.x += __shfl_xor_sync(0xffffffffu, nb.x, off);
        nb.y += __shfl_xor_sync(0xffffffffu, nb.y, off);
        nb.z += __shfl_xor_sync(0xffffffffu, nb.z, off);
        nb.w += __shfl_xor_sync(0xffffffffu, nb.w, off);
    }
    // combine the warp pair through smem
    if (lane < 8) {
        float* d = &sred[warp][l*10];
        d[0] = dena; d[1] = denb;
        d[2] = na.x; d[3] = na.y; d[4] = na.z; d[5] = na.w;
        d[6] = nb.x; d[7] = nb.y; d[8] = nb.z; d[9] = nb.w;
    }
    __syncthreads();
    if (par == 0 && lane < 8) {
        const float* o = &sred[warp^1][l*10];
        float inva = 1.0f / (dena + o[0]);
        float invb = 1.0f / (denb + o[1]);
        *(float4*)&g_att[p*64 + ca] = make_float4(
            (na.x + o[2])*inva, (na.y + o[3])*inva,
            (na.z + o[4])*inva, (na.w + o[5])*inva);
        *(float4*)&g_att[p*64 + cb] = make_float4(
            (nb.x + o[6])*invb, (nb.y + o[7])*invb,
            (nb.z + o[8])*invb, (nb.w + o[9])*invb);
    }
}

// ---------------------------------------------------------------------------
// Kernel 3: fused epilogue, P=4 positions per warp (R10 best config),
// L1-resident __ldg weights.
// ---------------------------------------------------------------------------
__global__ void __launch_bounds__(256) k_epilogue(const float* __restrict__ b1,
                                                  const float* __restrict__ b2,
                                                  const float* __restrict__ ln_g,
                                                  const float* __restrict__ ln_b,
                                                  float* __restrict__ out) {
    __shared__ float sV[8*4*64];    // 8 KB
    __shared__ float sT[8*4*128];   // 16 KB
    int tid = threadIdx.x, warp = tid >> 5, lane = tid & 31;
    int pbase = blockIdx.x * 32 + warp * 4;
    if (pbase >= NSEG) return;
    int c0 = 2*lane, c1 = c0 + 1;
    float* mV = sV + warp*256;
    float* mT = sT + warp*512;

    #pragma unroll
    for (int u = 0; u < 4; ++u) {
        float2 a2 = *(const float2*)&g_att[(pbase+u)*64 + c0];
        mV[u*64 + c0] = a2.x; mV[u*64 + c1] = a2.y;
    }
    __syncwarp();

    // a = wo @ att
    float acc[4][2] = {};
    #pragma unroll 8
    for (int c = 0; c < 64; ++c) {
        float2 w = __ldg((const float2*)&g_wo_t[c*64 + c0]);
        #pragma unroll
        for (int u = 0; u < 4; ++u) {
            float hc = mV[u*64 + c];
            acc[u][0] = fmaf(w.x, hc, acc[u][0]);
            acc[u][1] = fmaf(w.y, hc, acc[u][1]);
        }
    }
    // x1 = a + x ; LN1
    float x1a[4], x1b[4], s0[4];
    #pragma unroll
    for (int u = 0; u < 4; ++u) {
        float2 xv = *(const float2*)&g_xt[(pbase+u)*64 + c0];
        x1a[u] = acc[u][0] + xv.x;
        x1b[u] = acc[u][1] + xv.y;
        s0[u] = x1a[u] + x1b[u];
    }
    #pragma unroll
    for (int off = 16; off; off >>= 1) {
        #pragma unroll
        for (int u = 0; u < 4; ++u) s0[u] += __shfl_xor_sync(0xffffffffu, s0[u], off);
    }
    float da[4], db[4], vs[4];
    #pragma unroll
    for (int u = 0; u < 4; ++u) {
        float mean = s0[u] * (1.0f/64.0f);
        da[u] = x1a[u] - mean; db[u] = x1b[u] - mean;
        vs[u] = da[u]*da[u] + db[u]*db[u];
    }
    #pragma unroll
    for (int off = 16; off; off >>= 1) {
        #pragma unroll
        for (int u = 0; u < 4; ++u) vs[u] += __shfl_xor_sync(0xffffffffu, vs[u], off);
    }
    float g0 = ln_g[c0], g1 = ln_g[c1], be0 = ln_b[c0], be1 = ln_b[c1];
    __syncwarp();   // all lanes done reading mV in the wo loop
    #pragma unroll
    for (int u = 0; u < 4; ++u) {
        float rstd = rsqrtf(vs[u] * (1.0f/64.0f) + LNEPS);
        mV[u*64 + c0] = da[u]*rstd*g0 + be0;
        mV[u*64 + c1] = db[u]*rstd*g1 + be1;
    }
    __syncwarp();

    // t = gelu(w1 @ h1 + b1)
    float t[4][4] = {};
    #pragma unroll 8
    for (int c = 0; c < 64; ++c) {
        float2 wA = __ldg((const float2*)&g_w1_t[c*128 + c0]);
        float2 wB = __ldg((const float2*)&g_w1_t[c*128 + 64 + c0]);
        #pragma unroll
        for (int u = 0; u < 4; ++u) {
            float hc = mV[u*64 + c];
            t[u][0] = fmaf(wA.x, hc, t[u][0]); t[u][1] = fmaf(wA.y, hc, t[u][1]);
            t[u][2] = fmaf(wB.x, hc, t[u][2]); t[u][3] = fmaf(wB.y, hc, t[u][3]);
        }
    }
    const float RS2 = 0.70710678118654752f;
    float bb0 = b1[c0], bb1 = b1[c1], bb2 = b1[64+c0], bb3 = b1[64+c1];
    #pragma unroll
    for (int u = 0; u < 4; ++u) {
        float v0 = t[u][0] + bb0, v1 = t[u][1] + bb1;
        float v2 = t[u][2] + bb2, v3 = t[u][3] + bb3;
        mT[u*128 + c0]      = 0.5f*v0*(1.f + erff(v0*RS2));
        mT[u*128 + c1]      = 0.5f*v1*(1.f + erff(v1*RS2));
        mT[u*128 + 64 + c0] = 0.5f*v2*(1.f + erff(v2*RS2));
        mT[u*128 + 64 + c1] = 0.5f*v3*(1.f + erff(v3*RS2));
    }
    __syncwarp();

    // out = w2 @ t + b2 + x1
    float o[4][2] = {};
    #pragma unroll 8
    for (int f = 0; f < 128; ++f) {
        float2 w = __ldg((const float2*)&g_w2_t[f*64 + c0]);
        #pragma unroll
        for (int u = 0; u < 4; ++u) {
            float tf = mT[u*128 + f];
            o[u][0] = fmaf(w.x, tf, o[u][0]);
            o[u][1] = fmaf(w.y, tf, o[u][1]);
        }
    }
    float ob0 = b2[c0], ob1 = b2[c1];
    #pragma unroll
    for (int u = 0; u < 4; ++u) {
        int p = pbase + u;
        out[c0*NSEG + p] = o[u][0] + ob0 + x1a[u];
        out[c1*NSEG + p] = o[u][1] + ob1 + x1b[u];
    }
}

// ---------------------------------------------------------------------------
// Launch. Inputs: x, wq, wk, wv, wo, w1, b1, w2, b2, ln0_g, ln0_b,
// ln1_g, ln1_b, quad_w, out_idx, in_idx.
// ---------------------------------------------------------------------------
extern "C" void kernel_launch(void* const* d_in, const int* in_sizes, int n_in,
                              void* d_out, int out_size) {
    const float* x      = (const float*)d_in[0];
    const float* wq     = (const float*)d_in[1];
    const float* wk     = (const float*)d_in[2];
    const float* wv     = (const float*)d_in[3];
    const float* wmo    = (const float*)d_in[4];
    const float* w1     = (const float*)d_in[5];
    const float* b1     = (const float*)d_in[6];
    const float* w2     = (const float*)d_in[7];
    const float* b2     = (const float*)d_in[8];
    const float* ln0_g  = (const float*)d_in[9];
    const float* ln0_b  = (const float*)d_in[10];
    const float* ln1_g  = (const float*)d_in[11];
    const float* ln1_b  = (const float*)d_in[12];
    const float* quad_w = (const float*)d_in[13];
    const int*   out_idx= (const int*)d_in[14];
    const int*   in_idx = (const int*)d_in[15];
    float* out = (float*)d_out;

    int NNZ = in_sizes[14];
    int NE  = NNZ / 120;

    k_rowptr  <<<1, 1024>>>(out_idx, NE);
    k_prep    <<<30, 256>>>(x, wq, wk, wv, wmo, w1, w2);
    k_pay     <<<dim3(61, 15), 256>>>(in_idx, quad_w);
    k_ln_qkv  <<<229, 256>>>(ln0_g, ln0_b);
    k_attn    <<<1830, 256>>>();
    k_epilogue<<<229, 256>>>(b1, b2, ln1_g, ln1_b, out);
}

// round 15
// speedup vs baseline: 1.1872x; 1.0191x over previous
#include <cuda_runtime.h>
#include <math.h>

#define NLAT 61
#define NLON 120
#define NSEG (NLAT*NLON)      // 7320
#define CCH  64
#define ATT_SCALE 0.25f       // 1/sqrt(16)
#define LNEPS 1e-6f
// worst-case padded payload entries: (61*7*120 + 61*8) * 120 < 6.21M
#define EPAY_MAX 6400000

// Scratch (allocation-free rule: __device__ globals)
__device__ float g_xt [NSEG*CCH];    // x transposed to [p][c]
__device__ float g_q  [NSEG*CCH];    // pre-scaled by ATT_SCALE
__device__ float g_kv [NSEG*2*CCH];  // interleaved: [p][0:64]=k, [p][64:128]=v
__device__ float g_att[NSEG*CCH];
__device__ int   g_row_start[NLAT+1];  // original edge-row prefix
__device__ int   g_row_lenp [NLAT];    // padded row length (multiple of 8)
__device__ int   g_row_basep[NLAT];    // padded payload prefix (entry units)
__device__ int2  g_epay[EPAY_MAX];     // (kv byte offset, quad_w bits), seg-contiguous
// transposed weights: lane-contiguous layouts
__device__ float g_wq_t[4096];
__device__ float g_wk_t[4096];
__device__ float g_wv_t[4096];
__device__ float g_wo_t[4096];
__device__ float g_w1_t[8192];      // [c*128+f]
__device__ float g_w2_t[8192];      // [f*64+c]

// ---------------------------------------------------------------------------
// Kernel 0: per-output-row edge ranges + padded payload layout (1024 thr).
// ---------------------------------------------------------------------------
__global__ void k_rowptr(const int* __restrict__ out_idx, int NE) {
    __shared__ int cnt[NLAT];
    int tid = threadIdx.x;
    if (tid < NLAT) cnt[tid] = 0;
    __syncthreads();
    for (int e = tid; e < NE; e += blockDim.x) {
        int row = __ldg(&out_idx[e * 120]) / 120;
        atomicAdd(&cnt[row], 1);
    }
    __syncthreads();
    if (tid == 0) {
        int acc = 0, accp = 0;
        for (int r = 0; r < NLAT; ++r) {
            g_row_start[r] = acc; acc += cnt[r];
            int lenp = (cnt[r] + 7) & ~7;
            g_row_lenp[r]  = lenp;
            g_row_basep[r] = accp; accp += lenp * 120;
        }
        g_row_start[NLAT] = acc;
    }
}

// ---------------------------------------------------------------------------
// Kernel 0b: transpose x -> [p][c]; weights -> lane-contiguous layouts.
// ---------------------------------------------------------------------------
__global__ void k_prep(const float* __restrict__ x,
                       const float* __restrict__ wq, const float* __restrict__ wk,
                       const float* __restrict__ wv, const float* __restrict__ wo,
                       const float* __restrict__ w1, const float* __restrict__ w2) {
    int tid = threadIdx.x;
    if (blockIdx.x < 29) {
        int p = blockIdx.x * 256 + tid;
        if (p < NSEG) {
            #pragma unroll
            for (int c4 = 0; c4 < 64; c4 += 4) {
                float4 t;
                t.x = __ldcs(&x[(c4+0)*NSEG + p]);
                t.y = __ldcs(&x[(c4+1)*NSEG + p]);
                t.z = __ldcs(&x[(c4+2)*NSEG + p]);
                t.w = __ldcs(&x[(c4+3)*NSEG + p]);
                *(float4*)&g_xt[p*64 + c4] = t;
            }
        }
    } else {
        for (int i = tid; i < 4096; i += 256) {
            int o = i >> 6, c = i & 63;
            g_wq_t[c*64+o] = wq[i];
            g_wk_t[c*64+o] = wk[i];
            g_wv_t[c*64+o] = wv[i];
            g_wo_t[c*64+o] = wo[i];
        }
        for (int i = tid; i < 8192; i += 256) {    // w1: [f][c] -> [c][f]
            int f = i >> 6, c = i & 63;
            g_w1_t[c*128+f] = w1[i];
        }
        for (int i = tid; i < 8192; i += 256) {    // w2: [c][f] -> [f][c]
            int c = i >> 7, f = i & 127;
            g_w2_t[f*64+c] = w2[i];
        }
    }
}

// ---------------------------------------------------------------------------
// Kernel 0c: payload build, massively parallel (61 x 15 blocks).
// ---------------------------------------------------------------------------
__global__ void __launch_bounds__(256) k_pay(const int* __restrict__ in_idx,
                                             const float* __restrict__ quad_w) {
    int ho   = blockIdx.x;
    int rs   = g_row_start[ho];
    int len  = g_row_start[ho+1] - rs;
    int lenp = g_row_lenp[ho];
    int base = g_row_basep[ho];
    int tot  = lenp * 120;
    #pragma unroll 2
    for (int t = blockIdx.y * 256 + threadIdx.x; t < tot; t += gridDim.y * 256) {
        int j = t / 120, wo = t - j*120;           // j-major: coalesced in_idx reads
        int2 pay = make_int2(0, 0);
        if (j < len) {
            int s = __ldg(&in_idx[(rs+j)*120 + wo]);
            pay = make_int2(s * 512, __float_as_int(__ldg(&quad_w[s])));
        }
        g_epay[base + wo*lenp + j] = pay;
    }
}

// ---------------------------------------------------------------------------
// Kernel 1: LayerNorm0 + Q/K/V. TWO warps per 4-position group, split on
// the 64-channel contraction (chalf): each warp does 32 weight rows, then
// partials combine through smem. 16 positions/block, grid 458.
// ---------------------------------------------------------------------------
__global__ void __launch_bounds__(256) k_ln_qkv(const float* __restrict__ ln_g,
                                                const float* __restrict__ ln_b) {
    __shared__ float sH[4][256];        // per group: [u][c]
    __shared__ float sP[8][32][25];     // partials (+pad, conflict-free)
    int tid = threadIdx.x, warp = tid >> 5, lane = tid & 31;
    int grp = warp >> 1, chalf = warp & 1;
    int pbase = blockIdx.x * 16 + grp * 4;
    bool valid = (pbase + 3 < NSEG);
    int pb = valid ? pbase : (NSEG - 4);
    int c0 = 2*lane, c1 = c0 + 1;
    float* mH = sH[grp];

    // LN for all 4 positions (redundant in the pair — cheap)
    float2 xv[4]; float s0[4];
    #pragma unroll
    for (int u = 0; u < 4; ++u) {
        xv[u] = *(const float2*)&g_xt[(pb+u)*64 + c0];
        s0[u] = xv[u].x + xv[u].y;
    }
    #pragma unroll
    for (int off = 16; off; off >>= 1) {
        #pragma unroll
        for (int u = 0; u < 4; ++u) s0[u] += __shfl_xor_sync(0xffffffffu, s0[u], off);
    }
    float da[4], db[4], vs[4];
    #pragma unroll
    for (int u = 0; u < 4; ++u) {
        float mean = s0[u] * (1.0f/64.0f);
        da[u] = xv[u].x - mean; db[u] = xv[u].y - mean;
        vs[u] = da[u]*da[u] + db[u]*db[u];
    }
    #pragma unroll
    for (int off = 16; off; off >>= 1) {
        #pragma unroll
        for (int u = 0; u < 4; ++u) vs[u] += __shfl_xor_sync(0xffffffffu, vs[u], off);
    }
    float g0 = ln_g[c0], g1 = ln_g[c1], be0 = ln_b[c0], be1 = ln_b[c1];
    #pragma unroll
    for (int uu = 0; uu < 2; ++uu) {    // write only this warp's u-half
        int u = 2*chalf + uu;
        float rstd = rsqrtf(vs[u] * (1.0f/64.0f) + LNEPS);
        mH[u*64 + c0] = da[u]*rstd*g0 + be0;
        mH[u*64 + c1] = db[u]*rstd*g1 + be1;
    }
    __syncthreads();

    // GEMM over this warp's 32-channel half
    int cbeg = chalf * 32;
    float aq[4][2] = {}, ak[4][2] = {}, av[4][2] = {};
    #pragma unroll 8
    for (int cc = 0; cc < 32; ++cc) {
        int c = cbeg + cc;
        float2 wq2 = __ldg((const float2*)&g_wq_t[c*64 + c0]);
        float2 wk2 = __ldg((const float2*)&g_wk_t[c*64 + c0]);
        float2 wv2 = __ldg((const float2*)&g_wv_t[c*64 + c0]);
        #pragma unroll
        for (int u = 0; u < 4; ++u) {
            float hc = mH[u*64 + c];
            aq[u][0] = fmaf(wq2.x, hc, aq[u][0]); aq[u][1] = fmaf(wq2.y, hc, aq[u][1]);
            ak[u][0] = fmaf(wk2.x, hc, ak[u][0]); ak[u][1] = fmaf(wk2.y, hc, ak[u][1]);
            av[u][0] = fmaf(wv2.x, hc, av[u][0]); av[u][1] = fmaf(wv2.y, hc, av[u][1]);
        }
    }
    // combine the c-halves
    {
        float* d = sP[warp][lane];
        #pragma unroll
        for (int u = 0; u < 4; ++u) {
            d[u*2]      = aq[u][0]; d[u*2+1]      = aq[u][1];
            d[8 + u*2]  = ak[u][0]; d[8 + u*2+1]  = ak[u][1];
            d[16 + u*2] = av[u][0]; d[16 + u*2+1] = av[u][1];
        }
    }
    __syncthreads();
    {
        const float* o = sP[warp^1][lane];
        #pragma unroll
        for (int u = 0; u < 4; ++u) {
            aq[u][0] += o[u*2];      aq[u][1] += o[u*2+1];
            ak[u][0] += o[8 + u*2];  ak[u][1] += o[8 + u*2+1];
            av[u][0] += o[16 + u*2]; av[u][1] += o[16 + u*2+1];
        }
    }
    if (valid) {
        #pragma unroll
        for (int uu = 0; uu < 2; ++uu) {   // store this warp's u-half
            int u = 2*chalf + uu;
            int p = pb + u;
            *(float2*)&g_q [p*64  + c0] =
                make_float2(aq[u][0]*ATT_SCALE, aq[u][1]*ATT_SCALE);
            *(float2*)&g_kv[p*128 + c0]      = make_float2(ak[u][0], ak[u][1]);
            *(float2*)&g_kv[p*128 + 64 + c0] = make_float2(av[u][0], av[u][1]);
        }
    }
}

// ---------------------------------------------------------------------------
// Kernel 2: neighborhood attention, TWO warps per segment (4 segs/block,
// grid 1830), 4 edges/instruction, line-floor k/v loads. (R12 config.)
// ---------------------------------------------------------------------------
__global__ void __launch_bounds__(256) k_attn() {
    __shared__ float sred[8][80];         // per warp: 8 lanes x 10 partials
    int b = blockIdx.x;
    int bp = (b & 1) ? (1829 - (b >> 1)) : (b >> 1);  // heavy pole rows first
    int warp = threadIdx.x >> 5, lane = threadIdx.x & 31;
    int p = bp * 4 + (warp >> 1);
    int par = warp & 1;                   // which half of the edge stream
    int ho = p / 120, wo = p - ho * 120;
    int quarter = lane >> 3;              // edge slot within group-of-4
    int l = lane & 7;
    int ca = 4*l;                         // heads 0/1 channels
    int cb = 32 + 4*l;                    // heads 2/3 channels

    float4 qa = *(const float4*)&g_q[p*64 + ca];
    float4 qb = *(const float4*)&g_q[p*64 + cb];

    int lenp = g_row_lenp[ho];
    const int2* pay = &g_epay[g_row_basep[ho] + wo*lenp + quarter];

    float dena = 0.f, denb = 0.f;
    float4 na = make_float4(0.f,0.f,0.f,0.f);
    float4 nb = make_float4(0.f,0.f,0.f,0.f);

    const char* kvb = (const char*)g_kv;
    int ngrp = lenp >> 2;                 // groups of 4 edges; ngrp even
    #pragma unroll 1
    for (int i = 2*par; i < ngrp; i += 4) {   // this warp: groups i, i+1
        int2 p0 = __ldg(&pay[(i  )*4]);
        int2 p1 = __ldg(&pay[(i+1)*4]);
        const char* k0 = kvb + p0.x;
        const char* k1 = kvb + p1.x;
        float4 ka0 = *(const float4*)(k0 + ca*4);
        float4 kb0 = *(const float4*)(k0 + cb*4);
        float4 va0 = *(const float4*)(k0 + 256 + ca*4);
        float4 vb0 = *(const float4*)(k0 + 256 + cb*4);
        float4 ka1 = *(const float4*)(k1 + ca*4);
        float4 kb1 = *(const float4*)(k1 + cb*4);
        float4 va1 = *(const float4*)(k1 + 256 + ca*4);
        float4 vb1 = *(const float4*)(k1 + 256 + cb*4);

        float sa0 = ka0.x*qa.x + ka0.y*qa.y + ka0.z*qa.z + ka0.w*qa.w;
        float sb0 = kb0.x*qb.x + kb0.y*qb.y + kb0.z*qb.z + kb0.w*qb.w;
        float sa1 = ka1.x*qa.x + ka1.y*qa.y + ka1.z*qa.z + ka1.w*qa.w;
        float sb1 = kb1.x*qb.x + kb1.y*qb.y + kb1.z*qb.z + kb1.w*qb.w;
        sa0 += __shfl_xor_sync(0xffffffffu, sa0, 1);
        sb0 += __shfl_xor_sync(0xffffffffu, sb0, 1);
        sa1 += __shfl_xor_sync(0xffffffffu, sa1, 1);
        sb1 += __shfl_xor_sync(0xffffffffu, sb1, 1);
        sa0 += __shfl_xor_sync(0xffffffffu, sa0, 2);
        sb0 += __shfl_xor_sync(0xffffffffu, sb0, 2);
        sa1 += __shfl_xor_sync(0xffffffffu, sa1, 2);
        sb1 += __shfl_xor_sync(0xffffffffu, sb1, 2);
        float w0 = __int_as_float(p0.y);
        float w1 = __int_as_float(p1.y);
        float pa0 = __expf(sa0) * w0, pb0 = __expf(sb0) * w0;
        float pa1 = __expf(sa1) * w1, pb1 = __expf(sb1) * w1;
        dena += pa0; denb += pb0;
        na.x = fmaf(pa0, va0.x, na.x); na.y = fmaf(pa0, va0.y, na.y);
        na.z = fmaf(pa0, va0.z, na.z); na.w = fmaf(pa0, va0.w, na.w);
        nb.x = fmaf(pb0, vb0.x, nb.x); nb.y = fmaf(pb0, vb0.y, nb.y);
        nb.z = fmaf(pb0, vb0.z, nb.z); nb.w = fmaf(pb0, vb0.w, nb.w);
        dena += pa1; denb += pb1;
        na.x = fmaf(pa1, va1.x, na.x); na.y = fmaf(pa1, va1.y, na.y);
        na.z = fmaf(pa1, va1.z, na.z); na.w = fmaf(pa1, va1.w, na.w);
        nb.x = fmaf(pb1, vb1.x, nb.x); nb.y = fmaf(pb1, vb1.y, nb.y);
        nb.z = fmaf(pb1, vb1.z, nb.z); nb.w = fmaf(pb1, vb1.w, nb.w);
    }
    // reduce across the four edge quarters (same l -> same channels)
    #pragma unroll
    for (int off = 8; off <= 16; off <<= 1) {
        dena += __shfl_xor_sync(0xffffffffu, dena, off);
        denb += __shfl_xor_sync(0xffffffffu, denb, off);
        na.x += __shfl_xor_sync(0xffffffffu, na.x, off);
        na.y += __shfl_xor_sync(0xffffffffu, na.y, off);
        na.z += __shfl_xor_sync(0xffffffffu, na.z, off);
        na.w += __shfl_xor_sync(0xffffffffu, na.w, off);
        nb.x += __shfl_xor_sync(0xffffffffu, nb.x, off);
        nb.y += __shfl_xor_sync(0xffffffffu, nb.y, off);
        nb.z += __shfl_xor_sync(0xffffffffu, nb.z, off);
        nb.w += __shfl_xor_sync(0xffffffffu, nb.w, off);
    }
    // combine the warp pair through smem
    if (lane < 8) {
        float* d = &sred[warp][l*10];
        d[0] = dena; d[1] = denb;
        d[2] = na.x; d[3] = na.y; d[4] = na.z; d[5] = na.w;
        d[6] = nb.x; d[7] = nb.y; d[8] = nb.z; d[9] = nb.w;
    }
    __syncthreads();
    if (par == 0 && lane < 8) {
        const float* o = &sred[warp^1][l*10];
        float inva = 1.0f / (dena + o[0]);
        float invb = 1.0f / (denb + o[1]);
        *(float4*)&g_att[p*64 + ca] = make_float4(
            (na.x + o[2])*inva, (na.y + o[3])*inva,
            (na.z + o[4])*inva, (na.w + o[5])*inva);
        *(float4*)&g_att[p*64 + cb] = make_float4(
            (nb.x + o[6])*invb, (nb.y + o[7])*invb,
            (nb.z + o[8])*invb, (nb.w + o[9])*invb);
    }
}

// ---------------------------------------------------------------------------
// Kernel 3: fused epilogue, TWO warps per 4-position group split on the
// contraction dim (c for wo/w1, f for w2), partials combined via smem.
// 16 positions/block, grid 458.
// ---------------------------------------------------------------------------
__global__ void __launch_bounds__(256) k_epilogue(const float* __restrict__ b1,
                                                  const float* __restrict__ b2,
                                                  const float* __restrict__ ln_g,
                                                  const float* __restrict__ ln_b,
                                                  float* __restrict__ out) {
    __shared__ float sV[4][256];        // per group: att / h1 [u][c]
    __shared__ float sT[4][512];        // per group: t [u][f]
    __shared__ float sP[8][32][17];     // partials (+pad)
    int tid = threadIdx.x, warp = tid >> 5, lane = tid & 31;
    int grp = warp >> 1, chalf = warp & 1;
    int pbase = blockIdx.x * 16 + grp * 4;
    bool valid = (pbase + 3 < NSEG);
    int pb = valid ? pbase : (NSEG - 4);
    int c0 = 2*lane, c1 = c0 + 1;
    float* mV = sV[grp];
    float* mT = sT[grp];
    int cbeg = chalf * 32;

    // load att, split by u-half
    #pragma unroll
    for (int uu = 0; uu < 2; ++uu) {
        int u = 2*chalf + uu;
        float2 a2 = *(const float2*)&g_att[(pb+u)*64 + c0];
        mV[u*64 + c0] = a2.x; mV[u*64 + c1] = a2.y;
    }
    __syncthreads();

    // GEMM1: a = wo @ att, partial over this warp's c-half
    float acc[4][2] = {};
    #pragma unroll 8
    for (int cc = 0; cc < 32; ++cc) {
        int c = cbeg + cc;
        float2 w = __ldg((const float2*)&g_wo_t[c*64 + c0]);
        #pragma unroll
        for (int u = 0; u < 4; ++u) {
            float hc = mV[u*64 + c];
            acc[u][0] = fmaf(w.x, hc, acc[u][0]);
            acc[u][1] = fmaf(w.y, hc, acc[u][1]);
        }
    }
    {
        float* d = sP[warp][lane];
        #pragma unroll
        for (int u = 0; u < 4; ++u) { d[u*2] = acc[u][0]; d[u*2+1] = acc[u][1]; }
    }
    __syncthreads();
    {
        const float* o = sP[warp^1][lane];
        #pragma unroll
        for (int u = 0; u < 4; ++u) { acc[u][0] += o[u*2]; acc[u][1] += o[u*2+1]; }
    }
    // x1 = a + x ; LN1 (redundant in the pair)
    float x1a[4], x1b[4], s0[4];
    #pragma unroll
    for (int u = 0; u < 4; ++u) {
        float2 xv = *(const float2*)&g_xt[(pb+u)*64 + c0];
        x1a[u] = acc[u][0] + xv.x;
        x1b[u] = acc[u][1] + xv.y;
        s0[u] = x1a[u] + x1b[u];
    }
    #pragma unroll
    for (int off = 16; off; off >>= 1) {
        #pragma unroll
        for (int u = 0; u < 4; ++u) s0[u] += __shfl_xor_sync(0xffffffffu, s0[u], off);
    }
    float da[4], db[4], vs[4];
    #pragma unroll
    for (int u = 0; u < 4; ++u) {
        float mean = s0[u] * (1.0f/64.0f);
        da[u] = x1a[u] - mean; db[u] = x1b[u] - mean;
        vs[u] = da[u]*da[u] + db[u]*db[u];
    }
    #pragma unroll
    for (int off = 16; off; off >>= 1) {
        #pragma unroll
        for (int u = 0; u < 4; ++u) vs[u] += __shfl_xor_sync(0xffffffffu, vs[u], off);
    }
    float g0 = ln_g[c0], g1 = ln_g[c1], be0 = ln_b[c0], be1 = ln_b[c1];
    __syncthreads();                    // partial reads done; mV/sP reusable
    #pragma unroll
    for (int uu = 0; uu < 2; ++uu) {    // write h1, split by u
        int u = 2*chalf + uu;
        float rstd = rsqrtf(vs[u] * (1.0f/64.0f) + LNEPS);
        mV[u*64 + c0] = da[u]*rstd*g0 + be0;
        mV[u*64 + c1] = db[u]*rstd*g1 + be1;
    }
    __syncthreads();

    // GEMM2: t = w1 @ h1 + b1, partial over this warp's c-half
    float t[4][4] = {};
    #pragma unroll 8
    for (int cc = 0; cc < 32; ++cc) {
        int c = cbeg + cc;
        float2 wA = __ldg((const float2*)&g_w1_t[c*128 + c0]);
        float2 wB = __ldg((const float2*)&g_w1_t[c*128 + 64 + c0]);
        #pragma unroll
        for (int u = 0; u < 4; ++u) {
            float hc = mV[u*64 + c];
            t[u][0] = fmaf(wA.x, hc, t[u][0]); t[u][1] = fmaf(wA.y, hc, t[u][1]);
            t[u][2] = fmaf(wB.x, hc, t[u][2]); t[u][3] = fmaf(wB.y, hc, t[u][3]);
        }
    }
    {
        float* d = sP[warp][lane];
        #pragma unroll
        for (int u = 0; u < 4; ++u) {
            d[u*4] = t[u][0]; d[u*4+1] = t[u][1]; d[u*4+2] = t[u][2]; d[u*4+3] = t[u][3];
        }
    }
    __syncthreads();
    const float RS2 = 0.70710678118654752f;
    float bb0 = b1[c0], bb1 = b1[c1], bb2 = b1[64+c0], bb3 = b1[64+c1];
    {
        const float* o = sP[warp^1][lane];
        #pragma unroll
        for (int uu = 0; uu < 2; ++uu) {   // GELU + mT only for own u-half
            int u = 2*chalf + uu;
            float v0 = t[u][0] + o[u*4]   + bb0;
            float v1 = t[u][1] + o[u*4+1] + bb1;
            float v2 = t[u][2] + o[u*4+2] + bb2;
            float v3 = t[u][3] + o[u*4+3] + bb3;
            mT[u*128 + c0]      = 0.5f*v0*(1.f + erff(v0*RS2));
            mT[u*128 + c1]      = 0.5f*v1*(1.f + erff(v1*RS2));
            mT[u*128 + 64 + c0] = 0.5f*v2*(1.f + erff(v2*RS2));
            mT[u*128 + 64 + c1] = 0.5f*v3*(1.f + erff(v3*RS2));
        }
    }
    __syncthreads();

    // GEMM3: out = w2 @ t + b2 + x1, partial over this warp's f-half
    int fbeg = chalf * 64;
    float o2[4][2] = {};
    #pragma unroll 8
    for (int ff = 0; ff < 64; ++ff) {
        int f = fbeg + ff;
        float2 w = __ldg((const float2*)&g_w2_t[f*64 + c0]);
        #pragma unroll
        for (int u = 0; u < 4; ++u) {
            float tf = mT[u*128 + f];
            o2[u][0] = fmaf(w.x, tf, o2[u][0]);
            o2[u][1] = fmaf(w.y, tf, o2[u][1]);
        }
    }
    {
        float* d = sP[warp][lane];
        #pragma unroll
        for (int u = 0; u < 4; ++u) { d[u*2] = o2[u][0]; d[u*2+1] = o2[u][1]; }
    }
    __syncthreads();
    if (valid) {
        const float* o = sP[warp^1][lane];
        float ob0 = b2[c0], ob1 = b2[c1];
        #pragma unroll
        for (int uu = 0; uu < 2; ++uu) {   // store this warp's u-half
            int u = 2*chalf + uu;
            int p = pb + u;
            out[c0*NSEG + p] = o2[u][0] + o[u*2]   + ob0 + x1a[u];
            out[c1*NSEG + p] = o2[u][1] + o[u*2+1] + ob1 + x1b[u];
        }
    }
}

// ---------------------------------------------------------------------------
// Launch. Inputs: x, wq, wk, wv, wo, w1, b1, w2, b2, ln0_g, ln0_b,
// ln1_g, ln1_b, quad_w, out_idx, in_idx.
// ---------------------------------------------------------------------------
extern "C" void kernel_launch(void* const* d_in, const int* in_sizes, int n_in,
                              void* d_out, int out_size) {
    const float* x      = (const float*)d_in[0];
    const float* wq     = (const float*)d_in[1];
    const float* wk     = (const float*)d_in[2];
    const float* wv     = (const float*)d_in[3];
    const float* wmo    = (const float*)d_in[4];
    const float* w1     = (const float*)d_in[5];
    const float* b1     = (const float*)d_in[6];
    const float* w2     = (const float*)d_in[7];
    const float* b2     = (const float*)d_in[8];
    const float* ln0_g  = (const float*)d_in[9];
    const float* ln0_b  = (const float*)d_in[10];
    const float* ln1_g  = (const float*)d_in[11];
    const float* ln1_b  = (const float*)d_in[12];
    const float* quad_w = (const float*)d_in[13];
    const int*   out_idx= (const int*)d_in[14];
    const int*   in_idx = (const int*)d_in[15];
    float* out = (float*)d_out;

    int NNZ = in_sizes[14];
    int NE  = NNZ / 120;

    k_rowptr  <<<1, 1024>>>(out_idx, NE);
    k_prep    <<<30, 256>>>(x, wq, wk, wv, wmo, w1, w2);
    k_pay     <<<dim3(61, 15), 256>>>(in_idx, quad_w);
    k_ln_qkv  <<<458, 256>>>(ln0_g, ln0_b);
    k_attn    <<<1830, 256>>>();
    k_epilogue<<<458, 256>>>(b1, b2, ln1_g, ln1_b, out);
}

// round 16
// speedup vs baseline: 1.3476x; 1.1351x over previous
#include <cuda_runtime.h>
#include <math.h>

#define NLAT 61
#define NLON 120
#define NSEG (NLAT*NLON)      // 7320
#define CCH  64
#define ATT_SCALE 0.25f       // 1/sqrt(16)
#define LNEPS 1e-6f
// worst-case padded payload entries: (61*7*120 + 61*8) * 120 < 6.21M
#define EPAY_MAX 6400000

// Scratch (allocation-free rule: __device__ globals)
__device__ float g_xt [NSEG*CCH];    // x transposed to [p][c]
__device__ float g_q  [NSEG*CCH];    // pre-scaled by ATT_SCALE
__device__ float g_kv [NSEG*2*CCH];  // interleaved: [p][0:64]=k, [p][64:128]=v
__device__ float g_att[NSEG*CCH];
__device__ int   g_row_start[NLAT+1];  // original edge-row prefix
__device__ int   g_row_lenp [NLAT];    // padded row length (multiple of 8)
__device__ int   g_row_basep[NLAT];    // padded payload prefix (entry units)
__device__ int2  g_epay[EPAY_MAX];     // (kv byte offset, quad_w bits), seg-contiguous
// transposed weights: lane-contiguous layouts
__device__ float g_wq_t[4096];
__device__ float g_wk_t[4096];
__device__ float g_wv_t[4096];
__device__ float g_wo_t[4096];
__device__ float g_w1_t[8192];      // [c*128+f]
__device__ float g_w2_t[8192];      // [f*64+c]

// ---------------------------------------------------------------------------
// Kernel: per-output-row edge ranges + padded payload layout (stream C).
// ---------------------------------------------------------------------------
__global__ void k_rowptr(const int* __restrict__ out_idx, int NE) {
    __shared__ int cnt[NLAT];
    int tid = threadIdx.x;
    if (tid < NLAT) cnt[tid] = 0;
    __syncthreads();
    for (int e = tid; e < NE; e += blockDim.x) {
        int row = __ldg(&out_idx[e * 120]) / 120;
        atomicAdd(&cnt[row], 1);
    }
    __syncthreads();
    if (tid == 0) {
        int acc = 0, accp = 0;
        for (int r = 0; r < NLAT; ++r) {
            g_row_start[r] = acc; acc += cnt[r];
            int lenp = (cnt[r] + 7) & ~7;
            g_row_lenp[r]  = lenp;
            g_row_basep[r] = accp; accp += lenp * 120;
        }
        g_row_start[NLAT] = acc;
    }
}

// ---------------------------------------------------------------------------
// Kernel: weight transposes only (stream B, 1 block).
// ---------------------------------------------------------------------------
__global__ void k_wprep(const float* __restrict__ wq, const float* __restrict__ wk,
                        const float* __restrict__ wv, const float* __restrict__ wo,
                        const float* __restrict__ w1, const float* __restrict__ w2) {
    int tid = threadIdx.x;
    for (int i = tid; i < 4096; i += 256) {
        int o = i >> 6, c = i & 63;
        g_wq_t[c*64+o] = wq[i];
        g_wk_t[c*64+o] = wk[i];
        g_wv_t[c*64+o] = wv[i];
        g_wo_t[c*64+o] = wo[i];
    }
    for (int i = tid; i < 8192; i += 256) {    // w1: [f][c] -> [c][f]
        int f = i >> 6, c = i & 63;
        g_w1_t[c*128+f] = w1[i];
    }
    for (int i = tid; i < 8192; i += 256) {    // w2: [c][f] -> [f][c]
        int c = i >> 7, f = i & 127;
        g_w2_t[f*64+c] = w2[i];
    }
}

// ---------------------------------------------------------------------------
// Kernel: payload build, massively parallel (61 x 15 blocks, stream C).
// ---------------------------------------------------------------------------
__global__ void __launch_bounds__(256) k_pay(const int* __restrict__ in_idx,
                                             const float* __restrict__ quad_w) {
    int ho   = blockIdx.x;
    int rs   = g_row_start[ho];
    int len  = g_row_start[ho+1] - rs;
    int lenp = g_row_lenp[ho];
    int base = g_row_basep[ho];
    int tot  = lenp * 120;
    #pragma unroll 2
    for (int t = blockIdx.y * 256 + threadIdx.x; t < tot; t += gridDim.y * 256) {
        int j = t / 120, wo = t - j*120;           // j-major: coalesced in_idx reads
        int2 pay = make_int2(0, 0);
        if (j < len) {
            int s = __ldg(&in_idx[(rs+j)*120 + wo]);
            pay = make_int2(s * 512, __float_as_int(__ldg(&quad_w[s])));
        }
        g_epay[base + wo*lenp + j] = pay;
    }
}

// ---------------------------------------------------------------------------
// Kernel: fused x-transpose + LayerNorm0 + Q/K/V. Block stages its 16x64
// x-tile from strided x (coalesced float4), writes the g_xt residual copy,
// does LN in-tile, then the validated split-GEMM: TWO warps per 4-position
// group, split on the 64-channel contraction, partials via smem.
// ---------------------------------------------------------------------------
__global__ void __launch_bounds__(256) k_lnq(const float* __restrict__ x,
                                             const float* __restrict__ ln_g,
                                             const float* __restrict__ ln_b) {
    __shared__ float sXT[16*68 + 4];    // [p][c] tile, stride 68 (pad)
    __shared__ float sP[8][32][25];     // partials (+pad, conflict-free)
    int tid = threadIdx.x, warp = tid >> 5, lane = tid & 31;
    int pblk = blockIdx.x * 16;

    // stage x tile transposed: thread = (channel c, 4 consecutive positions)
    {
        int c = tid >> 2, q = tid & 3;
        int pl = pblk + q*4;
        if (pl > NSEG - 4) pl = NSEG - 4;          // clamp tail (NSEG % 4 == 0)
        float4 v = *(const float4*)&x[c*NSEG + pl];
        int r0 = q*4;
        sXT[(r0+0)*68 + c] = v.x;
        sXT[(r0+1)*68 + c] = v.y;
        sXT[(r0+2)*68 + c] = v.z;
        sXT[(r0+3)*68 + c] = v.w;
    }
    __syncthreads();
    // residual copy g_xt[p][c] (raw x, before LN overwrites the tile)
    {
        int pL = tid >> 4, c4 = (tid & 15) * 4;
        int pg = pblk + pL;
        if (pg < NSEG) {
            float4 w = make_float4(sXT[pL*68 + c4],     sXT[pL*68 + c4 + 1],
                                   sXT[pL*68 + c4 + 2], sXT[pL*68 + c4 + 3]);
            *(float4*)&g_xt[pg*64 + c4] = w;
        }
    }

    int grp = warp >> 1, chalf = warp & 1;
    int rbase = grp * 4;
    int c0 = 2*lane, c1 = c0 + 1;

    // LN for the group's 4 rows (both warps of the pair compute; cheap)
    float2 xv[4]; float s0[4];
    #pragma unroll
    for (int u = 0; u < 4; ++u) {
        xv[u] = *(const float2*)&sXT[(rbase+u)*68 + c0];
        s0[u] = xv[u].x + xv[u].y;
    }
    #pragma unroll
    for (int off = 16; off; off >>= 1) {
        #pragma unroll
        for (int u = 0; u < 4; ++u) s0[u] += __shfl_xor_sync(0xffffffffu, s0[u], off);
    }
    float da[4], db[4], vs[4];
    #pragma unroll
    for (int u = 0; u < 4; ++u) {
        float mean = s0[u] * (1.0f/64.0f);
        da[u] = xv[u].x - mean; db[u] = xv[u].y - mean;
        vs[u] = da[u]*da[u] + db[u]*db[u];
    }
    #pragma unroll
    for (int off = 16; off; off >>= 1) {
        #pragma unroll
        for (int u = 0; u < 4; ++u) vs[u] += __shfl_xor_sync(0xffffffffu, vs[u], off);
    }
    float g0 = ln_g[c0], g1 = ln_g[c1], be0 = ln_b[c0], be1 = ln_b[c1];
    __syncthreads();                    // raw-x reads (g_xt copy + xv) done
    #pragma unroll
    for (int uu = 0; uu < 2; ++uu) {    // overwrite tile with h, own u-half
        int u = 2*chalf + uu;
        float rstd = rsqrtf(vs[u] * (1.0f/64.0f) + LNEPS);
        sXT[(rbase+u)*68 + c0] = da[u]*rstd*g0 + be0;
        sXT[(rbase+u)*68 + c1] = db[u]*rstd*g1 + be1;
    }
    __syncthreads();

    // GEMM over this warp's 32-channel half
    int cbeg = chalf * 32;
    float aq[4][2] = {}, ak[4][2] = {}, av[4][2] = {};
    #pragma unroll 8
    for (int cc = 0; cc < 32; ++cc) {
        int c = cbeg + cc;
        float2 wq2 = __ldg((const float2*)&g_wq_t[c*64 + c0]);
        float2 wk2 = __ldg((const float2*)&g_wk_t[c*64 + c0]);
        float2 wv2 = __ldg((const float2*)&g_wv_t[c*64 + c0]);
        #pragma unroll
        for (int u = 0; u < 4; ++u) {
            float hc = sXT[(rbase+u)*68 + c];
            aq[u][0] = fmaf(wq2.x, hc, aq[u][0]); aq[u][1] = fmaf(wq2.y, hc, aq[u][1]);
            ak[u][0] = fmaf(wk2.x, hc, ak[u][0]); ak[u][1] = fmaf(wk2.y, hc, ak[u][1]);
            av[u][0] = fmaf(wv2.x, hc, av[u][0]); av[u][1] = fmaf(wv2.y, hc, av[u][1]);
        }
    }
    // combine the c-halves
    {
        float* d = sP[warp][lane];
        #pragma unroll
        for (int u = 0; u < 4; ++u) {
            d[u*2]      = aq[u][0]; d[u*2+1]      = aq[u][1];
            d[8 + u*2]  = ak[u][0]; d[8 + u*2+1]  = ak[u][1];
            d[16 + u*2] = av[u][0]; d[16 + u*2+1] = av[u][1];
        }
    }
    __syncthreads();
    {
        const float* o = sP[warp^1][lane];
        #pragma unroll
        for (int u = 0; u < 4; ++u) {
            aq[u][0] += o[u*2];      aq[u][1] += o[u*2+1];
            ak[u][0] += o[8 + u*2];  ak[u][1] += o[8 + u*2+1];
            av[u][0] += o[16 + u*2]; av[u][1] += o[16 + u*2+1];
        }
    }
    #pragma unroll
    for (int uu = 0; uu < 2; ++uu) {    // store this warp's u-half
        int u = 2*chalf + uu;
        int p = pblk + rbase + u;
        if (p < NSEG) {
            *(float2*)&g_q [p*64  + c0] =
                make_float2(aq[u][0]*ATT_SCALE, aq[u][1]*ATT_SCALE);
            *(float2*)&g_kv[p*128 + c0]      = make_float2(ak[u][0], ak[u][1]);
            *(float2*)&g_kv[p*128 + 64 + c0] = make_float2(av[u][0], av[u][1]);
        }
    }
}

// ---------------------------------------------------------------------------
// Kernel: neighborhood attention, TWO warps per segment (4 segs/block,
// grid 1830), 4 edges/instruction, line-floor k/v loads. (R12 config.)
// ---------------------------------------------------------------------------
__global__ void __launch_bounds__(256) k_attn() {
    __shared__ float sred[8][80];         // per warp: 8 lanes x 10 partials
    int b = blockIdx.x;
    int bp = (b & 1) ? (1829 - (b >> 1)) : (b >> 1);  // heavy pole rows first
    int warp = threadIdx.x >> 5, lane = threadIdx.x & 31;
    int p = bp * 4 + (warp >> 1);
    int par = warp & 1;                   // which half of the edge stream
    int ho = p / 120, wo = p - ho * 120;
    int quarter = lane >> 3;              // edge slot within group-of-4
    int l = lane & 7;
    int ca = 4*l;                         // heads 0/1 channels
    int cb = 32 + 4*l;                    // heads 2/3 channels

    float4 qa = *(const float4*)&g_q[p*64 + ca];
    float4 qb = *(const float4*)&g_q[p*64 + cb];

    int lenp = g_row_lenp[ho];
    const int2* pay = &g_epay[g_row_basep[ho] + wo*lenp + quarter];

    float dena = 0.f, denb = 0.f;
    float4 na = make_float4(0.f,0.f,0.f,0.f);
    float4 nb = make_float4(0.f,0.f,0.f,0.f);

    const char* kvb = (const char*)g_kv;
    int ngrp = lenp >> 2;                 // groups of 4 edges; ngrp even
    #pragma unroll 1
    for (int i = 2*par; i < ngrp; i += 4) {   // this warp: groups i, i+1
        int2 p0 = __ldg(&pay[(i  )*4]);
        int2 p1 = __ldg(&pay[(i+1)*4]);
        const char* k0 = kvb + p0.x;
        const char* k1 = kvb + p1.x;
        float4 ka0 = *(const float4*)(k0 + ca*4);
        float4 kb0 = *(const float4*)(k0 + cb*4);
        float4 va0 = *(const float4*)(k0 + 256 + ca*4);
        float4 vb0 = *(const float4*)(k0 + 256 + cb*4);
        float4 ka1 = *(const float4*)(k1 + ca*4);
        float4 kb1 = *(const float4*)(k1 + cb*4);
        float4 va1 = *(const float4*)(k1 + 256 + ca*4);
        float4 vb1 = *(const float4*)(k1 + 256 + cb*4);

        float sa0 = ka0.x*qa.x + ka0.y*qa.y + ka0.z*qa.z + ka0.w*qa.w;
        float sb0 = kb0.x*qb.x + kb0.y*qb.y + kb0.z*qb.z + kb0.w*qb.w;
        float sa1 = ka1.x*qa.x + ka1.y*qa.y + ka1.z*qa.z + ka1.w*qa.w;
        float sb1 = kb1.x*qb.x + kb1.y*qb.y + kb1.z*qb.z + kb1.w*qb.w;
        sa0 += __shfl_xor_sync(0xffffffffu, sa0, 1);
        sb0 += __shfl_xor_sync(0xffffffffu, sb0, 1);
        sa1 += __shfl_xor_sync(0xffffffffu, sa1, 1);
        sb1 += __shfl_xor_sync(0xffffffffu, sb1, 1);
        sa0 += __shfl_xor_sync(0xffffffffu, sa0, 2);
        sb0 += __shfl_xor_sync(0xffffffffu, sb0, 2);
        sa1 += __shfl_xor_sync(0xffffffffu, sa1, 2);
        sb1 += __shfl_xor_sync(0xffffffffu, sb1, 2);
        float w0 = __int_as_float(p0.y);
        float w1 = __int_as_float(p1.y);
        float pa0 = __expf(sa0) * w0, pb0 = __expf(sb0) * w0;
        float pa1 = __expf(sa1) * w1, pb1 = __expf(sb1) * w1;
        dena += pa0; denb += pb0;
        na.x = fmaf(pa0, va0.x, na.x); na.y = fmaf(pa0, va0.y, na.y);
        na.z = fmaf(pa0, va0.z, na.z); na.w = fmaf(pa0, va0.w, na.w);
        nb.x = fmaf(pb0, vb0.x, nb.x); nb.y = fmaf(pb0, vb0.y, nb.y);
        nb.z = fmaf(pb0, vb0.z, nb.z); nb.w = fmaf(pb0, vb0.w, nb.w);
        dena += pa1; denb += pb1;
        na.x = fmaf(pa1, va1.x, na.x); na.y = fmaf(pa1, va1.y, na.y);
        na.z = fmaf(pa1, va1.z, na.z); na.w = fmaf(pa1, va1.w, na.w);
        nb.x = fmaf(pb1, vb1.x, nb.x); nb.y = fmaf(pb1, vb1.y, nb.y);
        nb.z = fmaf(pb1, vb1.z, nb.z); nb.w = fmaf(pb1, vb1.w, nb.w);
    }
    // reduce across the four edge quarters (same l -> same channels)
    #pragma unroll
    for (int off = 8; off <= 16; off <<= 1) {
        dena += __shfl_xor_sync(0xffffffffu, dena, off);
        denb += __shfl_xor_sync(0xffffffffu, denb, off);
        na.x += __shfl_xor_sync(0xffffffffu, na.x, off);
        na.y += __shfl_xor_sync(0xffffffffu, na.y, off);
        na.z += __shfl_xor_sync(0xffffffffu, na.z, off);
        na.w += __shfl_xor_sync(0xffffffffu, na.w, off);
        nb.x += __shfl_xor_sync(0xffffffffu, nb.x, off);
        nb.y += __shfl_xor_sync(0xffffffffu, nb.y, off);
        nb.z += __shfl_xor_sync(0xffffffffu, nb.z, off);
        nb.w += __shfl_xor_sync(0xffffffffu, nb.w, off);
    }
    // combine the warp pair through smem
    if (lane < 8) {
        float* d = &sred[warp][l*10];
        d[0] = dena; d[1] = denb;
        d[2] = na.x; d[3] = na.y; d[4] = na.z; d[5] = na.w;
        d[6] = nb.x; d[7] = nb.y; d[8] = nb.z; d[9] = nb.w;
    }
    __syncthreads();
    if (par == 0 && lane < 8) {
        const float* o = &sred[warp^1][l*10];
        float inva = 1.0f / (dena + o[0]);
        float invb = 1.0f / (denb + o[1]);
        *(float4*)&g_att[p*64 + ca] = make_float4(
            (na.x + o[2])*inva, (na.y + o[3])*inva,
            (na.z + o[4])*inva, (na.w + o[5])*inva);
        *(float4*)&g_att[p*64 + cb] = make_float4(
            (nb.x + o[6])*invb, (nb.y + o[7])*invb,
            (nb.z + o[8])*invb, (nb.w + o[9])*invb);
    }
}

// ---------------------------------------------------------------------------
// Kernel: fused epilogue, TWO warps per 4-position group split on the
// contraction dim (c for wo/w1, f for w2), partials combined via smem.
// ---------------------------------------------------------------------------
__global__ void __launch_bounds__(256) k_epilogue(const float* __restrict__ b1,
                                                  const float* __restrict__ b2,
                                                  const float* __restrict__ ln_g,
                                                  const float* __restrict__ ln_b,
                                                  float* __restrict__ out) {
    __shared__ float sV[4][256];        // per group: att / h1 [u][c]
    __shared__ float sT[4][512];        // per group: t [u][f]
    __shared__ float sP[8][32][17];     // partials (+pad)
    int tid = threadIdx.x, warp = tid >> 5, lane = tid & 31;
    int grp = warp >> 1, chalf = warp & 1;
    int pbase = blockIdx.x * 16 + grp * 4;
    bool valid = (pbase + 3 < NSEG);
    int pb = valid ? pbase : (NSEG - 4);
    int c0 = 2*lane, c1 = c0 + 1;
    float* mV = sV[grp];
    float* mT = sT[grp];
    int cbeg = chalf * 32;

    // load att, split by u-half
    #pragma unroll
    for (int uu = 0; uu < 2; ++uu) {
        int u = 2*chalf + uu;
        float2 a2 = *(const float2*)&g_att[(pb+u)*64 + c0];
        mV[u*64 + c0] = a2.x; mV[u*64 + c1] = a2.y;
    }
    __syncthreads();

    // GEMM1: a = wo @ att, partial over this warp's c-half
    float acc[4][2] = {};
    #pragma unroll 8
    for (int cc = 0; cc < 32; ++cc) {
        int c = cbeg + cc;
        float2 w = __ldg((const float2*)&g_wo_t[c*64 + c0]);
        #pragma unroll
        for (int u = 0; u < 4; ++u) {
            float hc = mV[u*64 + c];
            acc[u][0] = fmaf(w.x, hc, acc[u][0]);
            acc[u][1] = fmaf(w.y, hc, acc[u][1]);
        }
    }
    {
        float* d = sP[warp][lane];
        #pragma unroll
        for (int u = 0; u < 4; ++u) { d[u*2] = acc[u][0]; d[u*2+1] = acc[u][1]; }
    }
    __syncthreads();
    {
        const float* o = sP[warp^1][lane];
        #pragma unroll
        for (int u = 0; u < 4; ++u) { acc[u][0] += o[u*2]; acc[u][1] += o[u*2+1]; }
    }
    // x1 = a + x ; LN1 (redundant in the pair)
    float x1a[4], x1b[4], s0[4];
    #pragma unroll
    for (int u = 0; u < 4; ++u) {
        float2 xv = *(const float2*)&g_xt[(pb+u)*64 + c0];
        x1a[u] = acc[u][0] + xv.x;
        x1b[u] = acc[u][1] + xv.y;
        s0[u] = x1a[u] + x1b[u];
    }
    #pragma unroll
    for (int off = 16; off; off >>= 1) {
        #pragma unroll
        for (int u = 0; u < 4; ++u) s0[u] += __shfl_xor_sync(0xffffffffu, s0[u], off);
    }
    float da[4], db[4], vs[4];
    #pragma unroll
    for (int u = 0; u < 4; ++u) {
        float mean = s0[u] * (1.0f/64.0f);
        da[u] = x1a[u] - mean; db[u] = x1b[u] - mean;
        vs[u] = da[u]*da[u] + db[u]*db[u];
    }
    #pragma unroll
    for (int off = 16; off; off >>= 1) {
        #pragma unroll
        for (int u = 0; u < 4; ++u) vs[u] += __shfl_xor_sync(0xffffffffu, vs[u], off);
    }
    float g0 = ln_g[c0], g1 = ln_g[c1], be0 = ln_b[c0], be1 = ln_b[c1];
    __syncthreads();                    // partial reads done; mV/sP reusable
    #pragma unroll
    for (int uu = 0; uu < 2; ++uu) {    // write h1, split by u
        int u = 2*chalf + uu;
        float rstd = rsqrtf(vs[u] * (1.0f/64.0f) + LNEPS);
        mV[u*64 + c0] = da[u]*rstd*g0 + be0;
        mV[u*64 + c1] = db[u]*rstd*g1 + be1;
    }
    __syncthreads();

    // GEMM2: t = w1 @ h1 + b1, partial over this warp's c-half
    float t[4][4] = {};
    #pragma unroll 8
    for (int cc = 0; cc < 32; ++cc) {
        int c = cbeg + cc;
        float2 wA = __ldg((const float2*)&g_w1_t[c*128 + c0]);
        float2 wB = __ldg((const float2*)&g_w1_t[c*128 + 64 + c0]);
        #pragma unroll
        for (int u = 0; u < 4; ++u) {
            float hc = mV[u*64 + c];
            t[u][0] = fmaf(wA.x, hc, t[u][0]); t[u][1] = fmaf(wA.y, hc, t[u][1]);
            t[u][2] = fmaf(wB.x, hc, t[u][2]); t[u][3] = fmaf(wB.y, hc, t[u][3]);
        }
    }
    {
        float* d = sP[warp][lane];
        #pragma unroll
        for (int u = 0; u < 4; ++u) {
            d[u*4] = t[u][0]; d[u*4+1] = t[u][1]; d[u*4+2] = t[u][2]; d[u*4+3] = t[u][3];
        }
    }
    __syncthreads();
    const float RS2 = 0.70710678118654752f;
    float bb0 = b1[c0], bb1 = b1[c1], bb2 = b1[64+c0], bb3 = b1[64+c1];
    {
        const float* o = sP[warp^1][lane];
        #pragma unroll
        for (int uu = 0; uu < 2; ++uu) {   // GELU + mT only for own u-half
            int u = 2*chalf + uu;
            float v0 = t[u][0] + o[u*4]   + bb0;
            float v1 = t[u][1] + o[u*4+1] + bb1;
            float v2 = t[u][2] + o[u*4+2] + bb2;
            float v3 = t[u][3] + o[u*4+3] + bb3;
            mT[u*128 + c0]      = 0.5f*v0*(1.f + erff(v0*RS2));
            mT[u*128 + c1]      = 0.5f*v1*(1.f + erff(v1*RS2));
            mT[u*128 + 64 + c0] = 0.5f*v2*(1.f + erff(v2*RS2));
            mT[u*128 + 64 + c1] = 0.5f*v3*(1.f + erff(v3*RS2));
        }
    }
    __syncthreads();

    // GEMM3: out = w2 @ t + b2 + x1, partial over this warp's f-half
    int fbeg = chalf * 64;
    float o2[4][2] = {};
    #pragma unroll 8
    for (int ff = 0; ff < 64; ++ff) {
        int f = fbeg + ff;
        float2 w = __ldg((const float2*)&g_w2_t[f*64 + c0]);
        #pragma unroll
        for (int u = 0; u < 4; ++u) {
            float tf = mT[u*128 + f];
            o2[u][0] = fmaf(w.x, tf, o2[u][0]);
            o2[u][1] = fmaf(w.y, tf, o2[u][1]);
        }
    }
    {
        float* d = sP[warp][lane];
        #pragma unroll
        for (int u = 0; u < 4; ++u) { d[u*2] = o2[u][0]; d[u*2+1] = o2[u][1]; }
    }
    __syncthreads();
    if (valid) {
        const float* o = sP[warp^1][lane];
        float ob0 = b2[c0], ob1 = b2[c1];
        #pragma unroll
        for (int uu = 0; uu < 2; ++uu) {   // store this warp's u-half
            int u = 2*chalf + uu;
            int p = pb + u;
            out[c0*NSEG + p] = o2[u][0] + o[u*2]   + ob0 + x1a[u];
            out[c1*NSEG + p] = o2[u][1] + o[u*2+1] + ob1 + x1b[u];
        }
    }
}

// ---------------------------------------------------------------------------
// Launch with a forked graph: stream B = weight transposes, stream C =
// edge tables (rowptr -> pay), main stream = lnq -> attn -> epilogue.
// Fork/join via events (the documented capture-compatible pattern). Streams
// and events are created lazily on the first (non-capture) call; the work
// launched is identical on every call.
// Inputs: x, wq, wk, wv, wo, w1, b1, w2, b2, ln0_g, ln0_b, ln1_g, ln1_b,
// quad_w, out_idx, in_idx.
// ---------------------------------------------------------------------------
extern "C" void kernel_launch(void* const* d_in, const int* in_sizes, int n_in,
                              void* d_out, int out_size) {
    const float* x      = (const float*)d_in[0];
    const float* wq     = (const float*)d_in[1];
    const float* wk     = (const float*)d_in[2];
    const float* wv     = (const float*)d_in[3];
    const float* wmo    = (const float*)d_in[4];
    const float* w1     = (const float*)d_in[5];
    const float* b1     = (const float*)d_in[6];
    const float* w2     = (const float*)d_in[7];
    const float* b2     = (const float*)d_in[8];
    const float* ln0_g  = (const float*)d_in[9];
    const float* ln0_b  = (const float*)d_in[10];
    const float* ln1_g  = (const float*)d_in[11];
    const float* ln1_b  = (const float*)d_in[12];
    const float* quad_w = (const float*)d_in[13];
    const int*   out_idx= (const int*)d_in[14];
    const int*   in_idx = (const int*)d_in[15];
    float* out = (float*)d_out;

    int NNZ = in_sizes[14];
    int NE  = NNZ / 120;

    static cudaStream_t sB = 0, sC = 0;
    static cudaEvent_t  eF = 0, eB = 0, eC = 0;
    if (sB == 0) {
        cudaStreamCreateWithFlags(&sB, cudaStreamNonBlocking);
        cudaStreamCreateWithFlags(&sC, cudaStreamNonBlocking);
        cudaEventCreateWithFlags(&eF, cudaEventDisableTiming);
        cudaEventCreateWithFlags(&eB, cudaEventDisableTiming);
        cudaEventCreateWithFlags(&eC, cudaEventDisableTiming);
    }

    // fork from the captured (default) stream
    cudaEventRecord(eF, 0);
    cudaStreamWaitEvent(sB, eF, 0);
    cudaStreamWaitEvent(sC, eF, 0);

    k_wprep <<<1, 256, 0, sB>>>(wq, wk, wv, wmo, w1, w2);
    cudaEventRecord(eB, sB);

    k_rowptr<<<1, 1024, 0, sC>>>(out_idx, NE);
    k_pay   <<<dim3(61, 15), 256, 0, sC>>>(in_idx, quad_w);
    cudaEventRecord(eC, sC);

    // main chain: lnq needs weights (B); attn additionally needs tables (C)
    cudaStreamWaitEvent(0, eB, 0);
    k_lnq     <<<458, 256>>>(x, ln0_g, ln0_b);
    cudaStreamWaitEvent(0, eC, 0);
    k_attn    <<<1830, 256>>>();
    k_epilogue<<<458, 256>>>(b1, b2, ln1_g, ln1_b, out);
}